// round 7
// baseline (speedup 1.0000x reference)
#include <cuda_runtime.h>
#include <math.h>

// Problem constants (PerturbationAttention): delta [B, C, D] fp32, k = 256
#define B_DIM 2048
#define C_DIM 512
#define D_DIM 256
#define K_SEL 256
#define SIG_BLOCKS 592   // 148 SMs * 4 resident blocks of 512 threads

// Scratch (no allocations allowed): sigma buffer (4 MB) + per-block maxima.
__device__ float g_sigma[B_DIM * C_DIM];
__device__ float g_blockmax[SIG_BLOCKS];

// ---------------------------------------------------------------------------
// Kernel 1: sigma[r] = ||delta[r, :]||_2 for r in [0, B*C).
// Warp-per-row, grid-stride, 4 blocks/SM resident (64 warps/SM).
// Each lane loads 2 float4 (32 B) -> 1 KiB per warp per row, fully coalesced.
// ---------------------------------------------------------------------------
__global__ void __launch_bounds__(512, 4)
pa_sigma_kernel(const float* __restrict__ delta)
{
    const int lane = threadIdx.x & 31;
    const int wid  = threadIdx.x >> 5;
    const int warps_per_block = 16;
    const int gwarp = blockIdx.x * warps_per_block + wid;
    const int warp_stride = SIG_BLOCKS * warps_per_block;   // 9472

    float lmax = 0.0f;

    #pragma unroll 2
    for (int row = gwarp; row < B_DIM * C_DIM; row += warp_stride) {
        const float4* p = reinterpret_cast<const float4*>(delta + (size_t)row * D_DIM);
        float4 a = p[lane];
        float4 b = p[lane + 32];
        float s = a.x * a.x + a.y * a.y + a.z * a.z + a.w * a.w
                + b.x * b.x + b.y * b.y + b.z * b.z + b.w * b.w;

        #pragma unroll
        for (int o = 16; o > 0; o >>= 1)
            s += __shfl_xor_sync(0xffffffffu, s, o);

        float sig = sqrtf(s);
        if (lane == 0) g_sigma[row] = sig;
        lmax = fmaxf(lmax, sig);
    }

    __shared__ float smax[16];
    if (lane == 0) smax[wid] = lmax;
    __syncthreads();
    if (wid == 0) {
        float v = (lane < warps_per_block) ? smax[lane] : 0.0f;
        #pragma unroll
        for (int o = 8; o > 0; o >>= 1)
            v = fmaxf(v, __shfl_xor_sync(0xffffffffu, v, o));
        if (lane == 0) g_blockmax[blockIdx.x] = v;
    }
}

__device__ __forceinline__ float tanh_approx(float x) {
    float r;
    asm("tanh.approx.f32 %0, %1;" : "=f"(r) : "f"(x));
    return r;
}

// ---------------------------------------------------------------------------
// Kernel 2: TWO batch rows per block (rows 2b, 2b+1), 512 threads.
// Per row: t = tanh(1 - sigma/gmax); att = softmax_C(t); zero the K_SEL
// smallest att (ties -> lowest index). Radix select on float bits with
// dynamic leading-byte skip (keys share sign+exponent, so pass 1 is dead).
// ---------------------------------------------------------------------------
__global__ void __launch_bounds__(512)
pa_select_kernel(float* __restrict__ out)
{
    const int i    = threadIdx.x;       // column 0..511
    const int lane = i & 31;
    const int w    = i >> 5;            // warp 0..15
    const int rA   = 2 * blockIdx.x;
    const int rB   = rA + 1;

    __shared__ float    s_redA[16], s_redB[16];
    __shared__ unsigned s_histA[256], s_histB[256];
    __shared__ unsigned s_wsumA[8], s_wsumB[8];
    __shared__ unsigned s_binA, s_exclA, s_binB, s_exclB;
    __shared__ int      s_wcntA[16], s_wcntB[16];

    // ---- global max over per-block maxima ----
    {
        float v = (i < SIG_BLOCKS) ? g_blockmax[i] : 0.0f;
        if (i + 512 < SIG_BLOCKS) v = fmaxf(v, g_blockmax[i + 512]);
        #pragma unroll
        for (int o = 16; o > 0; o >>= 1)
            v = fmaxf(v, __shfl_xor_sync(0xffffffffu, v, o));
        if (lane == 0) s_redA[w] = v;
    }
    __syncthreads();
    float gmax = s_redA[0];
    #pragma unroll
    for (int j = 1; j < 16; j++) gmax = fmaxf(gmax, s_redA[j]);
    __syncthreads();

    const float tA = tanh_approx(1.0f - g_sigma[rA * C_DIM + i] / gmax);
    const float tB = tanh_approx(1.0f - g_sigma[rB * C_DIM + i] / gmax);

    // ---- block max AND min of t, both rows (one sync) ----
    float mA = tA, nA = tA, mB = tB, nB = tB;
    #pragma unroll
    for (int o = 16; o > 0; o >>= 1) {
        mA = fmaxf(mA, __shfl_xor_sync(0xffffffffu, mA, o));
        nA = fminf(nA, __shfl_xor_sync(0xffffffffu, nA, o));
        mB = fmaxf(mB, __shfl_xor_sync(0xffffffffu, mB, o));
        nB = fminf(nB, __shfl_xor_sync(0xffffffffu, nB, o));
    }
    if (lane == 0) { s_redA[w] = mA; s_redB[w] = mB; s_histA[w] = __float_as_uint(nA); s_histB[w] = __float_as_uint(nB); }
    __syncthreads();
    mA = s_redA[0]; mB = s_redB[0];
    nA = __uint_as_float(s_histA[0]); nB = __uint_as_float(s_histB[0]);
    #pragma unroll
    for (int j = 1; j < 16; j++) {
        mA = fmaxf(mA, s_redA[j]);  mB = fmaxf(mB, s_redB[j]);
        nA = fminf(nA, __uint_as_float(s_histA[j]));
        nB = fminf(nB, __uint_as_float(s_histB[j]));
    }
    __syncthreads();

    const float eA = __expf(tA - mA);
    const float eB = __expf(tB - mB);

    // ---- block sum of e, both rows (one sync) ----
    float sA = eA, sB = eB;
    #pragma unroll
    for (int o = 16; o > 0; o >>= 1) {
        sA += __shfl_xor_sync(0xffffffffu, sA, o);
        sB += __shfl_xor_sync(0xffffffffu, sB, o);
    }
    if (lane == 0) { s_redA[w] = sA; s_redB[w] = sB; }
    __syncthreads();
    sA = s_redA[0]; sB = s_redB[0];
    #pragma unroll
    for (int j = 1; j < 16; j++) { sA += s_redA[j]; sB += s_redB[j]; }
    __syncthreads();

    const float attA = eA / sA;
    const float attB = eB / sB;
    const unsigned keyA = __float_as_uint(attA);   // att > 0: bit order == value order
    const unsigned keyB = __float_as_uint(attB);

    // ---- bit-exact key bounds (free: att monotone in t, __expf(0)=1 exact) ----
    const unsigned kminA = __float_as_uint(__expf(nA - mA) / sA);
    const unsigned kmaxA = __float_as_uint(1.0f / sA);
    const unsigned kminB = __float_as_uint(__expf(nB - mB) / sB);
    const unsigned kmaxB = __float_as_uint(1.0f / sB);

    // shared leading bytes -> skip dead radix passes (cap at 3 => >=1 pass)
    const int nbA = min(3, __clz(kminA ^ kmaxA) >> 3);
    const int nbB = min(3, __clz(kminB ^ kmaxB) >> 3);
    const int nb  = min(nbA, nbB);
    const int start_shift = 24 - 8 * nb;

    unsigned prefixA = (nb == 0) ? 0u : (kminA >> (start_shift + 8));
    unsigned prefixB = (nb == 0) ? 0u : (kminB >> (start_shift + 8));
    unsigned kremA = K_SEL, kremB = K_SEL;

    for (int shift = start_shift; shift >= 0; shift -= 8) {
        // clear both histograms (512 threads, 512 bins)
        if (i < 256) s_histA[i] = 0u; else s_histB[i - 256] = 0u;
        __syncthreads();

        const bool inA = (shift == 24) || ((keyA >> (shift + 8)) == prefixA);
        const bool inB = (shift == 24) || ((keyB >> (shift + 8)) == prefixB);
        // warp-aggregated histogram updates
        {
            unsigned dA = inA ? ((keyA >> shift) & 255u) : 256u;
            unsigned gA = __match_any_sync(0xffffffffu, dA);
            if (inA && lane == (__ffs(gA) - 1u))
                atomicAdd(&s_histA[dA], (unsigned)__popc(gA));
            unsigned dB = inB ? ((keyB >> shift) & 255u) : 256u;
            unsigned gB = __match_any_sync(0xffffffffu, dB);
            if (inB && lane == (__ffs(gB) - 1u))
                atomicAdd(&s_histB[dB], (unsigned)__popc(gB));
        }
        __syncthreads();

        // scans: warps 0-7 scan row A bins, warps 8-15 row B bins
        unsigned h = 0u, incl = 0u;
        {
            h = (i < 256) ? s_histA[i] : s_histB[i - 256];
            unsigned x = h;
            #pragma unroll
            for (int o = 1; o < 32; o <<= 1) {
                unsigned y = __shfl_up_sync(0xffffffffu, x, o);
                if (lane >= o) x += y;
            }
            if (lane == 31) { if (w < 8) s_wsumA[w] = x; else s_wsumB[w - 8] = x; }
            incl = x;
        }
        __syncthreads();
        {
            const int ws = w & 7;
            unsigned off = 0u;
            #pragma unroll
            for (int j = 0; j < 8; j++) {
                unsigned v = (w < 8) ? s_wsumA[j] : s_wsumB[j];
                if (j < ws) off += v;
            }
            incl += off;
            unsigned excl = incl - h;
            if (i < 256) {
                if (incl >= kremA && excl < kremA) { s_binA = (unsigned)i; s_exclA = excl; }
            } else {
                if (incl >= kremB && excl < kremB) { s_binB = (unsigned)(i - 256); s_exclB = excl; }
            }
        }
        __syncthreads();

        prefixA = (prefixA << 8) | s_binA;  kremA -= s_exclA;
        prefixB = (prefixB << 8) | s_binB;  kremB -= s_exclB;
        // next write to s_bin*/s_excl* is 2+ syncs away; no extra sync needed
    }

    const unsigned TA = prefixA, TB = prefixB;       // k-th smallest key bits
    const unsigned tieA = kremA, tieB = kremB;       // #ties to zero (low idx first)

    // ---- tie ranks, both rows (one sync) ----
    const bool eqA = (keyA == TA);
    const bool eqB = (keyB == TB);
    const unsigned balA = __ballot_sync(0xffffffffu, eqA);
    const unsigned balB = __ballot_sync(0xffffffffu, eqB);
    if (lane == 0) { s_wcntA[w] = __popc(balA); s_wcntB[w] = __popc(balB); }
    __syncthreads();
    int woffA = 0, woffB = 0;
    #pragma unroll
    for (int j = 0; j < 16; j++) {
        if (j < w) { woffA += s_wcntA[j]; woffB += s_wcntB[j]; }
    }
    const unsigned lmask = (1u << lane) - 1u;
    const unsigned rankA = (unsigned)woffA + (unsigned)__popc(balA & lmask);
    const unsigned rankB = (unsigned)woffB + (unsigned)__popc(balB & lmask);

    const bool zA = (keyA < TA) || (eqA && rankA < tieA);
    const bool zB = (keyB < TB) || (eqB && rankB < tieB);
    out[rA * C_DIM + i] = zA ? 0.0f : attA;
    out[rB * C_DIM + i] = zB ? 0.0f : attB;
}

// ---------------------------------------------------------------------------
// Launch: two kernels, graph-capturable, allocation-free.
// ---------------------------------------------------------------------------
extern "C" void kernel_launch(void* const* d_in, const int* in_sizes, int n_in,
                              void* d_out, int out_size)
{
    const float* delta = (const float*)d_in[0];
    float* out = (float*)d_out;
    (void)in_sizes; (void)n_in; (void)out_size;

    pa_sigma_kernel<<<SIG_BLOCKS, 512>>>(delta);
    pa_select_kernel<<<B_DIM / 2, C_DIM>>>(out);
}